// round 9
// baseline (speedup 1.0000x reference)
#include <cuda_runtime.h>
#include <cuda_fp16.h>
#include <cstdint>

#define IN_CH   128
#define OUT_CH  128
#define NDEG    81
#define NCPT    17
#define P_TOT   6561
#define XB_STRIDE (IN_CH * P_TOT)

#define WROW 136                 // padded k-row length in fp16 (272 bytes)
#define WBLK (128 * WROW)        // per-degree elems (34816 B)
#define NT   3                   // 64-col tiles per CTA -> 588 CTAs = 2 waves

__device__ __align__(16) __half wA[NDEG * WBLK];

__device__ __forceinline__ unsigned smem_u32(const void* p) {
    unsigned a;
    asm("{ .reg .u64 t; cvta.to.shared.u64 t, %1; cvt.u32.u64 %0, t; }"
        : "=r"(a) : "l"(p));
    return a;
}

#define LDSM4(R, ADDR)                                                        \
    asm volatile("ldmatrix.sync.aligned.m8n8.x4.shared.b16 "                  \
                 "{%0,%1,%2,%3}, [%4];"                                       \
                 : "=r"((R)[0]), "=r"((R)[1]), "=r"((R)[2]), "=r"((R)[3])     \
                 : "r"(ADDR))

#define MMA16816(D, A, B0, B1)                                                \
    asm volatile("mma.sync.aligned.m16n8k16.row.col.f32.f16.f16.f32 "         \
                 "{%0,%1,%2,%3},{%4,%5,%6,%7},{%8,%9},{%0,%1,%2,%3};"         \
                 : "+f"((D)[0]), "+f"((D)[1]), "+f"((D)[2]), "+f"((D)[3])     \
                 : "r"((A)[0]), "r"((A)[1]), "r"((A)[2]), "r"((A)[3]),        \
                   "r"(B0), "r"(B1))

#define CPA16(DST, SRC)                                                       \
    asm volatile("cp.async.cg.shared.global [%0], [%1], 16;"                  \
                 :: "r"(DST), "l"(SRC))

// ---------------------------------------------------------------------------
// Kernel 1: interp + pack -> fp16 W in padded [o][k] layout (unchanged).
// ---------------------------------------------------------------------------
__global__ __launch_bounds__(256) void shconv_interp_pack(const float* __restrict__ w)
{
    __shared__ float anch[32][NCPT];
    const int o  = blockIdx.x >> 2;
    const int k0 = (blockIdx.x & 3) * 32;

    for (int e = threadIdx.x; e < 32 * NCPT; e += 256) {
        const int kk = e / NCPT, s = e % NCPT;
        anch[kk][s] = w[((k0 + kk) * OUT_CH + o) * NCPT + s];
    }
    __syncthreads();

    for (int e = threadIdx.x; e < NDEG * 32; e += 256) {
        const int l  = e >> 5;
        const int kk = e & 31;
        int s; float t;
        if (l < 75) { s = l / 5; t = (float)(l - s * 5) * 0.2f; }
        else        { s = 15;    t = (float)(l - 75) * 0.2f; }
        const float v = (1.0f - t) * anch[kk][s] + t * anch[kk][s + 1];
        wA[l * WBLK + o * WROW + k0 + kk] = __float2half_rn(v);
    }
}

// ---------------------------------------------------------------------------
// Kernel 2: single-sync-per-tile fp16 HMMA GEMM, warp-tile 16x32, NT=3.
//   D[128 o][64 c] = W * X    (fp16 inputs, fp32 accum)
// B double-buffered (STS(t) overlaps MMA(t-1) readers on other buffer);
// coloff triple-buffered (buffer index = tt since NT=3) so epilogue LDS of
// generation t never races the write of generation t+2 (two syncs apart).
// smem: W 34816 | B0 17408 | B1 17408 | coloff[3][64]
// ---------------------------------------------------------------------------
#define SM_W    0
#define SM_B0   34816
#define SM_B1   52224
#define SM_COL  69632
#define DSMEM   70400

__global__ __launch_bounds__(512, 2) void shconv_mma(const float* __restrict__ x,
                                                     float* __restrict__ out)
{
    const int l      = 80 - blockIdx.y;          // LPT: big degrees first
    const int ntiles = (l >> 1) + 1;
    const int t0     = blockIdx.x * NT;
    int nt = ntiles - t0;
    if (nt <= 0) return;
    if (nt > NT) nt = NT;

    extern __shared__ __align__(16) char sm[];
    int* coloff = (int*)(sm + SM_COL);           // [3][64]
    const unsigned sb = smem_u32(sm);

    const int tid  = threadIdx.x;
    const int lane = tid & 31;
    const int wid  = tid >> 5;
    const int span  = 2 * l + 1;
    const int ncols = 16 * span;

    // --- W: cp.async (2176 uint4) ---
    {
        const char* gw = (const char*)(wA + l * WBLK);
#pragma unroll
        for (int j = 0; j < 5; j++) {
            const int e = tid + 512 * j;
            if (e < 2176)
                CPA16(sb + SM_W + e * 16, gw + e * 16);
        }
        asm volatile("cp.async.commit_group;" ::: "memory");
    }

    // --- coloff for tile 0 -> buffer 0 ---
    if (tid < 64) {
        const int c  = t0 * 64 + tid;
        const int cc = c < ncols ? c : ncols - 1;
        const int b  = cc / span;
        coloff[tid] = b * XB_STRIDE + l * l + (cc - b * span);
    }
    asm volatile("cp.async.wait_group 0;" ::: "memory");
    __syncthreads();                              // coloff0 + W visible

    // --- X ownership: thread -> (col xc, k in [kb,kb+16)), eager fp16 pack ---
    const int xc = tid & 63;
    const int kb = (tid >> 6) * 16;
    unsigned xh[8];
    {
        const float* xp = x + coloff[xc];
#pragma unroll
        for (int m = 0; m < 8; m++) {
            const __half h0 = __float2half_rn(xp[(kb + 2 * m) * P_TOT]);
            const __half h1 = __float2half_rn(xp[(kb + 2 * m + 1) * P_TOT]);
            xh[m] = ((unsigned)__half_as_ushort(h1) << 16) | __half_as_ushort(h0);
        }
    }

    // --- fragment addresses: warp-tile 16 (m) x 32 (n) ---
    const int m_base = (wid >> 1) * 16;
    const int n_base = (wid & 1) * 32;
    const unsigned aoff = (unsigned)(m_base + (lane & 15)) * 272u + (unsigned)(lane >> 4) * 16u;
    const unsigned aW = sb + SM_W + aoff;
    const unsigned boff = (unsigned)(n_base + ((lane & 7) | ((lane >> 4) << 3))) * 272u
                        + (unsigned)((lane >> 3) & 1) * 16u;

    for (int tt = 0; tt < nt; tt++) {
        const unsigned bbase = (tt & 1) ? SM_B1 : SM_B0;
        char* bp = sm + bbase;

        // --- STS xh(tt) -> B[tt&1] (other buffer than MMA(tt-1) readers) ---
        {
            uint4 v0 = { xh[0], xh[1], xh[2], xh[3] };
            uint4 v1 = { xh[4], xh[5], xh[6], xh[7] };
            *(uint4*)(bp + xc * 272 + kb * 2)      = v0;
            *(uint4*)(bp + xc * 272 + kb * 2 + 16) = v1;
        }
        // --- coloff(tt+1) -> buffer tt+1 ---
        if (tt + 1 < nt && tid < 64) {
            const int c  = (t0 + tt + 1) * 64 + tid;
            const int cc = c < ncols ? c : ncols - 1;
            const int b  = cc / span;
            coloff[(tt + 1) * 64 + tid] = b * XB_STRIDE + l * l + (cc - b * span);
        }
        __syncthreads();        // the ONLY barrier per tile

        // --- LDG + convert X(tt+1) (lands during MMA below) ---
        if (tt + 1 < nt) {
            const float* xp = x + coloff[(tt + 1) * 64 + xc];
#pragma unroll
            for (int m = 0; m < 8; m++) {
                const __half h0 = __float2half_rn(xp[(kb + 2 * m) * P_TOT]);
                const __half h1 = __float2half_rn(xp[(kb + 2 * m + 1) * P_TOT]);
                xh[m] = ((unsigned)__half_as_ushort(h1) << 16) | __half_as_ushort(h0);
            }
        }

        // --- MMA: 8 k-steps x 4 nq from B[tt&1] ---
        const unsigned bB0 = sb + bbase + boff, bB1 = bB0 + 16u * 272u;
        float acc[4][4];
#pragma unroll
        for (int nq = 0; nq < 4; nq++)
#pragma unroll
            for (int j = 0; j < 4; j++) acc[nq][j] = 0.0f;

#pragma unroll
        for (int ks = 0; ks < 8; ks++) {
            const unsigned ko = (unsigned)ks * 32u;
            unsigned ah[4], b0[4], b1[4];
            LDSM4(ah, aW + ko);
            LDSM4(b0, bB0 + ko);
            LDSM4(b1, bB1 + ko);
            MMA16816(acc[0], ah, b0[0], b0[1]);
            MMA16816(acc[1], ah, b0[2], b0[3]);
            MMA16816(acc[2], ah, b1[0], b1[1]);
            MMA16816(acc[3], ah, b1[2], b1[3]);
        }

        // --- epilogue: coloff[tt] is safe until sync(tt+1) has passed ---
        const int c0t = (t0 + tt) * 64;
        const int r   = m_base + (lane >> 2);
#pragma unroll
        for (int nq = 0; nq < 4; nq++) {
            const int cc = n_base + nq * 8 + (lane & 3) * 2;
            if (c0t + cc < ncols) {
                const int off = coloff[tt * 64 + cc];
                out[off + r * P_TOT]       = acc[nq][0];
                out[off + (r + 8) * P_TOT] = acc[nq][2];
            }
            if (c0t + cc + 1 < ncols) {
                const int off = coloff[tt * 64 + cc + 1];
                out[off + r * P_TOT]       = acc[nq][1];
                out[off + (r + 8) * P_TOT] = acc[nq][3];
            }
        }
        // no trailing barrier: next STS targets the other B buffer, and
        // coloff generation tt is only rewritten two syncs from now.
    }
}

extern "C" void kernel_launch(void* const* d_in, const int* in_sizes, int n_in,
                              void* d_out, int out_size)
{
    const float* x = (const float*)d_in[0];      // [16,128,6561]
    const float* w = (const float*)d_in[1];      // [128,128,17,1]
    float* out = (float*)d_out;                  // [16,128,6561]

    cudaFuncSetAttribute(shconv_mma,
                         cudaFuncAttributeMaxDynamicSharedMemorySize, DSMEM);

    shconv_interp_pack<<<512, 256>>>(w);

    dim3 grid(14, NDEG);                         // 3-tile chunks x degrees
    shconv_mma<<<grid, 512, DSMEM>>>(x, out);
}

// round 10
// speedup vs baseline: 1.2402x; 1.2402x over previous
#include <cuda_runtime.h>
#include <cuda_fp16.h>
#include <cstdint>

#define IN_CH   128
#define OUT_CH  128
#define NDEG    81
#define NCPT    17
#define P_TOT   6561
#define XB_STRIDE (IN_CH * P_TOT)

#define WROW 136                 // padded k-row length in fp16 (272 bytes)
#define WBLK (128 * WROW)        // per-degree elems (34816 B)
#define NT   3                   // 64-col tiles per CTA -> 588 CTAs = 2 waves

__device__ __align__(16) __half wA[NDEG * WBLK];

__device__ __forceinline__ unsigned smem_u32(const void* p) {
    unsigned a;
    asm("{ .reg .u64 t; cvta.to.shared.u64 t, %1; cvt.u32.u64 %0, t; }"
        : "=r"(a) : "l"(p));
    return a;
}

#define LDSM4(R, ADDR)                                                        \
    asm volatile("ldmatrix.sync.aligned.m8n8.x4.shared.b16 "                  \
                 "{%0,%1,%2,%3}, [%4];"                                       \
                 : "=r"((R)[0]), "=r"((R)[1]), "=r"((R)[2]), "=r"((R)[3])     \
                 : "r"(ADDR))

#define MMA16816(D, A, B0, B1)                                                \
    asm volatile("mma.sync.aligned.m16n8k16.row.col.f32.f16.f16.f32 "         \
                 "{%0,%1,%2,%3},{%4,%5,%6,%7},{%8,%9},{%0,%1,%2,%3};"         \
                 : "+f"((D)[0]), "+f"((D)[1]), "+f"((D)[2]), "+f"((D)[3])     \
                 : "r"((A)[0]), "r"((A)[1]), "r"((A)[2]), "r"((A)[3]),        \
                   "r"(B0), "r"(B1))

#define CPA16(DST, SRC)                                                       \
    asm volatile("cp.async.cg.shared.global [%0], [%1], 16;"                  \
                 :: "r"(DST), "l"(SRC))

// ---------------------------------------------------------------------------
// Kernel 1: interp + pack -> fp16 W in padded [o][k] layout (unchanged).
// ---------------------------------------------------------------------------
__global__ __launch_bounds__(256) void shconv_interp_pack(const float* __restrict__ w)
{
    __shared__ float anch[32][NCPT];
    const int o  = blockIdx.x >> 2;
    const int k0 = (blockIdx.x & 3) * 32;

    for (int e = threadIdx.x; e < 32 * NCPT; e += 256) {
        const int kk = e / NCPT, s = e % NCPT;
        anch[kk][s] = w[((k0 + kk) * OUT_CH + o) * NCPT + s];
    }
    __syncthreads();

    for (int e = threadIdx.x; e < NDEG * 32; e += 256) {
        const int l  = e >> 5;
        const int kk = e & 31;
        int s; float t;
        if (l < 75) { s = l / 5; t = (float)(l - s * 5) * 0.2f; }
        else        { s = 15;    t = (float)(l - 75) * 0.2f; }
        const float v = (1.0f - t) * anch[kk][s] + t * anch[kk][s + 1];
        wA[l * WBLK + o * WROW + k0 + kk] = __float2half_rn(v);
    }
}

// ---------------------------------------------------------------------------
// Kernel 2: fp16 HMMA GEMM with smem-transposed COALESCED epilogue.
//   D[128 o][64 c] = W * X    (fp16 inputs, fp32 accum)
// Per tile: STS-B -> coloff(next gen) -> sync1 -> LDG/CVT(t+1) -> MMA
//           -> STS acc to EPI scratch -> sync2 -> coalesced LDS+STG.
// EPI pitch 72 floats: STS.64 conflict-free (4r+cc/2 distinct mod 32),
// LDS row-reads conflict-free. coloff: 3 generations (one per tile).
// smem: W 34816 | B 17408 | EPI 36864 | coloff[3][64]
// ---------------------------------------------------------------------------
#define SM_W    0
#define SM_B    34816
#define SM_EPI  52224
#define SM_COL  89088
#define DSMEM   89856

__global__ __launch_bounds__(512, 2) void shconv_mma(const float* __restrict__ x,
                                                     float* __restrict__ out)
{
    const int l      = 80 - blockIdx.y;          // LPT: big degrees first
    const int ntiles = (l >> 1) + 1;
    const int t0     = blockIdx.x * NT;
    int nt = ntiles - t0;
    if (nt <= 0) return;
    if (nt > NT) nt = NT;

    extern __shared__ __align__(16) char sm[];
    int*   coloff = (int*)(sm + SM_COL);         // [3][64]
    float* ep     = (float*)(sm + SM_EPI);       // [128][72]
    const unsigned sb = smem_u32(sm);

    const int tid  = threadIdx.x;
    const int lane = tid & 31;
    const int wid  = tid >> 5;
    const int span  = 2 * l + 1;
    const int ncols = 16 * span;

    // --- W: cp.async (2176 uint4) ---
    {
        const char* gw = (const char*)(wA + l * WBLK);
#pragma unroll
        for (int j = 0; j < 5; j++) {
            const int e = tid + 512 * j;
            if (e < 2176)
                CPA16(sb + SM_W + e * 16, gw + e * 16);
        }
        asm volatile("cp.async.commit_group;" ::: "memory");
    }

    // --- coloff for tile 0 -> generation 0 ---
    if (tid < 64) {
        const int c  = t0 * 64 + tid;
        const int cc = c < ncols ? c : ncols - 1;
        const int b  = cc / span;
        coloff[tid] = b * XB_STRIDE + l * l + (cc - b * span);
    }
    asm volatile("cp.async.wait_group 0;" ::: "memory");
    __syncthreads();

    // --- X ownership: thread -> (col xc, k in [kb,kb+16)), eager fp16 pack ---
    const int xc = tid & 63;
    const int kb = (tid >> 6) * 16;
    unsigned xh[8];
    {
        const float* xp = x + coloff[xc];
#pragma unroll
        for (int m = 0; m < 8; m++) {
            const __half h0 = __float2half_rn(xp[(kb + 2 * m) * P_TOT]);
            const __half h1 = __float2half_rn(xp[(kb + 2 * m + 1) * P_TOT]);
            xh[m] = ((unsigned)__half_as_ushort(h1) << 16) | __half_as_ushort(h0);
        }
    }

    // --- fragment addresses: warp-tile 16 (m) x 32 (n) ---
    const int m_base = (wid >> 1) * 16;
    const int n_base = (wid & 1) * 32;
    const unsigned aoff = (unsigned)(m_base + (lane & 15)) * 272u + (unsigned)(lane >> 4) * 16u;
    const unsigned aW = sb + SM_W + aoff;
    const unsigned boff = (unsigned)(n_base + ((lane & 7) | ((lane >> 4) << 3))) * 272u
                        + (unsigned)((lane >> 3) & 1) * 16u;
    const unsigned bB0 = sb + SM_B + boff, bB1 = bB0 + 16u * 272u;

    char* bp = sm + SM_B;

    // --- epilogue output mapping (thread-invariant): column ec, row base ob ---
    const int ec = tid & 63;
    const int ob = tid >> 6;                     // rows ob, ob+8, ..., ob+120

    for (int tt = 0; tt < nt; tt++) {
        // --- STS xh(tt) -> B ---
        {
            uint4 v0 = { xh[0], xh[1], xh[2], xh[3] };
            uint4 v1 = { xh[4], xh[5], xh[6], xh[7] };
            *(uint4*)(bp + xc * 272 + kb * 2)      = v0;
            *(uint4*)(bp + xc * 272 + kb * 2 + 16) = v1;
        }
        // --- coloff(tt+1) -> generation tt+1 ---
        if (tt + 1 < nt && tid < 64) {
            const int c  = (t0 + tt + 1) * 64 + tid;
            const int cc = c < ncols ? c : ncols - 1;
            const int b  = cc / span;
            coloff[(tt + 1) * 64 + tid] = b * XB_STRIDE + l * l + (cc - b * span);
        }
        __syncthreads();                          // sync1: B(tt)+coloff visible

        // --- LDG + convert X(tt+1) (lands during MMA below) ---
        if (tt + 1 < nt) {
            const float* xp = x + coloff[(tt + 1) * 64 + xc];
#pragma unroll
            for (int m = 0; m < 8; m++) {
                const __half h0 = __float2half_rn(xp[(kb + 2 * m) * P_TOT]);
                const __half h1 = __float2half_rn(xp[(kb + 2 * m + 1) * P_TOT]);
                xh[m] = ((unsigned)__half_as_ushort(h1) << 16) | __half_as_ushort(h0);
            }
        }

        // --- MMA: 8 k-steps x 4 nq ---
        float acc[4][4];
#pragma unroll
        for (int nq = 0; nq < 4; nq++)
#pragma unroll
            for (int j = 0; j < 4; j++) acc[nq][j] = 0.0f;

#pragma unroll
        for (int ks = 0; ks < 8; ks++) {
            const unsigned ko = (unsigned)ks * 32u;
            unsigned ah[4], b0[4], b1[4];
            LDSM4(ah, aW + ko);
            LDSM4(b0, bB0 + ko);
            LDSM4(b1, bB1 + ko);
            MMA16816(acc[0], ah, b0[0], b0[1]);
            MMA16816(acc[1], ah, b0[2], b0[3]);
            MMA16816(acc[2], ah, b1[0], b1[1]);
            MMA16816(acc[3], ah, b1[2], b1[3]);
        }

        // --- STS acc -> EPI scratch (pitch 72, conflict-free STS.64) ---
        {
            const int r = m_base + (lane >> 2);
#pragma unroll
            for (int nq = 0; nq < 4; nq++) {
                const int cc = n_base + nq * 8 + (lane & 3) * 2;
                float2 lo = { acc[nq][0], acc[nq][1] };
                float2 hi = { acc[nq][2], acc[nq][3] };
                *(float2*)&ep[r * 72 + cc]       = lo;
                *(float2*)&ep[(r + 8) * 72 + cc] = hi;
            }
        }
        __syncthreads();                          // sync2: EPI complete

        // --- coalesced epilogue: lanes sweep consecutive c -> 128B lines ---
        if ((t0 + tt) * 64 + ec < ncols) {
            float* op = out + coloff[tt * 64 + ec] + ob * P_TOT;
            const float* rp = ep + ob * 72 + ec;
#pragma unroll
            for (int j = 0; j < 16; j++)
                op[j * 8 * P_TOT] = rp[j * 8 * 72];
        }
        // no third barrier: next STS-B/coloff writes touch regions no longer
        // read (B re-written only by its own writer pattern after all warps
        // passed sync2; EPI re-written only after next sync1; coloff gen tt
        // never re-written within this CTA).
    }
}

extern "C" void kernel_launch(void* const* d_in, const int* in_sizes, int n_in,
                              void* d_out, int out_size)
{
    const float* x = (const float*)d_in[0];      // [16,128,6561]
    const float* w = (const float*)d_in[1];      // [128,128,17,1]
    float* out = (float*)d_out;                  // [16,128,6561]

    cudaFuncSetAttribute(shconv_mma,
                         cudaFuncAttributeMaxDynamicSharedMemorySize, DSMEM);

    shconv_interp_pack<<<512, 256>>>(w);

    dim3 grid(14, NDEG);                         // 3-tile chunks x degrees
    shconv_mma<<<grid, 512, DSMEM>>>(x, out);
}

// round 11
// speedup vs baseline: 1.3257x; 1.0689x over previous
#include <cuda_runtime.h>
#include <cuda_fp16.h>
#include <cstdint>

#define IN_CH   128
#define OUT_CH  128
#define NDEG    81
#define NCPT    17
#define P_TOT   6561
#define XB_STRIDE (IN_CH * P_TOT)

#define WROW 136                 // padded k-row length in fp16 (272 bytes)
#define WBLK (128 * WROW)        // per-degree elems (34816 B)
#define NT   3                   // 64-col tiles per CTA -> 588 CTAs = 2 waves

__device__ __align__(16) __half wA[NDEG * WBLK];

__device__ __forceinline__ unsigned smem_u32(const void* p) {
    unsigned a;
    asm("{ .reg .u64 t; cvta.to.shared.u64 t, %1; cvt.u32.u64 %0, t; }"
        : "=r"(a) : "l"(p));
    return a;
}

#define LDSM4(R, ADDR)                                                        \
    asm volatile("ldmatrix.sync.aligned.m8n8.x4.shared.b16 "                  \
                 "{%0,%1,%2,%3}, [%4];"                                       \
                 : "=r"((R)[0]), "=r"((R)[1]), "=r"((R)[2]), "=r"((R)[3])     \
                 : "r"(ADDR))

#define MMA16816(D, A, B0, B1)                                                \
    asm volatile("mma.sync.aligned.m16n8k16.row.col.f32.f16.f16.f32 "         \
                 "{%0,%1,%2,%3},{%4,%5,%6,%7},{%8,%9},{%0,%1,%2,%3};"         \
                 : "+f"((D)[0]), "+f"((D)[1]), "+f"((D)[2]), "+f"((D)[3])     \
                 : "r"((A)[0]), "r"((A)[1]), "r"((A)[2]), "r"((A)[3]),        \
                   "r"(B0), "r"(B1))

#define CPA16(DST, SRC)                                                       \
    asm volatile("cp.async.cg.shared.global [%0], [%1], 16;"                  \
                 :: "r"(DST), "l"(SRC))

// ---------------------------------------------------------------------------
// Kernel 1: interp + pack -> fp16 W in padded [o][k] layout (unchanged).
// ---------------------------------------------------------------------------
__global__ __launch_bounds__(256) void shconv_interp_pack(const float* __restrict__ w)
{
    __shared__ float anch[32][NCPT];
    const int o  = blockIdx.x >> 2;
    const int k0 = (blockIdx.x & 3) * 32;

    for (int e = threadIdx.x; e < 32 * NCPT; e += 256) {
        const int kk = e / NCPT, s = e % NCPT;
        anch[kk][s] = w[((k0 + kk) * OUT_CH + o) * NCPT + s];
    }
    __syncthreads();

    for (int e = threadIdx.x; e < NDEG * 32; e += 256) {
        const int l  = e >> 5;
        const int kk = e & 31;
        int s; float t;
        if (l < 75) { s = l / 5; t = (float)(l - s * 5) * 0.2f; }
        else        { s = 15;    t = (float)(l - 75) * 0.2f; }
        const float v = (1.0f - t) * anch[kk][s] + t * anch[kk][s + 1];
        wA[l * WBLK + o * WROW + k0 + kk] = __float2half_rn(v);
    }
}

// ---------------------------------------------------------------------------
// Kernel 2: 256-thread fp16 HMMA GEMM, W fragments HOISTED to registers.
//   D[128 o][64 c] = W * X    (fp16 inputs, fp32 accum)
// 8 warps, warp-tile 16m x 64n. A (W) ldmatrix'd ONCE per CTA (32 regs),
// then the W smem staging region is reused as the EPI transpose scratch.
// Per tile: STS-B + coloff(next) -> sync1 -> LDG/CVT(t+1) -> MMA(B-LDSM only)
//           -> STS acc to EPI -> sync2 -> coalesced LDS+STG.
// smem: Wstage/EPI 36864 | B 17408 | coloff[3][64]
// ---------------------------------------------------------------------------
#define SM_EPI  0
#define SM_B    36864
#define SM_COL  54272
#define DSMEM   55040

__global__ __launch_bounds__(256, 2) void shconv_mma(const float* __restrict__ x,
                                                     float* __restrict__ out)
{
    const int l      = 80 - blockIdx.y;          // LPT: big degrees first
    const int ntiles = (l >> 1) + 1;
    const int t0     = blockIdx.x * NT;
    int nt = ntiles - t0;
    if (nt <= 0) return;
    if (nt > NT) nt = NT;

    extern __shared__ __align__(16) char sm[];
    int*   coloff = (int*)(sm + SM_COL);         // [3][64]
    float* ep     = (float*)(sm + SM_EPI);       // [128][72] after hoist
    const unsigned sb = smem_u32(sm);

    const int tid  = threadIdx.x;
    const int lane = tid & 31;
    const int wid  = tid >> 5;
    const int span  = 2 * l + 1;
    const int ncols = 16 * span;

    // --- W: cp.async into the (soon to be EPI) staging region ---
    {
        const char* gw = (const char*)(wA + l * WBLK);
#pragma unroll
        for (int j = 0; j < 9; j++) {
            const int e = tid + 256 * j;
            if (e < 2176)
                CPA16(sb + SM_EPI + e * 16, gw + e * 16);
        }
        asm volatile("cp.async.commit_group;" ::: "memory");
    }

    // --- coloff for tile 0 -> generation 0 ---
    if (tid < 64) {
        const int c  = t0 * 64 + tid;
        const int cc = c < ncols ? c : ncols - 1;
        const int b  = cc / span;
        coloff[tid] = b * XB_STRIDE + l * l + (cc - b * span);
    }
    asm volatile("cp.async.wait_group 0;" ::: "memory");
    __syncthreads();

    // --- HOIST: ldmatrix all 8 k-step A fragments once (W tile-invariant) ---
    const int m_base = wid * 16;
    unsigned aF[8][4];
    {
        const unsigned aoff = (unsigned)(m_base + (lane & 15)) * 272u
                            + (unsigned)(lane >> 4) * 16u;
        const unsigned aW = sb + SM_EPI + aoff;
#pragma unroll
        for (int ks = 0; ks < 8; ks++)
            LDSM4(aF[ks], aW + (unsigned)ks * 32u);
    }

    // --- X ownership: col xc, k in [kb,kb+32); eager fp16 pack (16 words) ---
    const int xc = tid & 63;
    const int kb = (tid >> 6) * 32;
    unsigned xh[16];
    {
        const float* xp = x + coloff[xc];
#pragma unroll
        for (int m = 0; m < 16; m++) {
            const __half h0 = __float2half_rn(xp[(kb + 2 * m) * P_TOT]);
            const __half h1 = __float2half_rn(xp[(kb + 2 * m + 1) * P_TOT]);
            xh[m] = ((unsigned)__half_as_ushort(h1) << 16) | __half_as_ushort(h0);
        }
    }

    // --- B fragment addresses: 4 n-groups of 16 cols each ---
    const unsigned boff = (unsigned)(((lane & 7) | ((lane >> 4) << 3))) * 272u
                        + (unsigned)((lane >> 3) & 1) * 16u;
    const unsigned bB = sb + SM_B + boff;        // + g*16*272 + ks*32

    char* bp = sm + SM_B;
    const int ec = tid & 63;                     // epilogue column
    const int ob = tid >> 6;                     // epilogue row base (0..3)

    for (int tt = 0; tt < nt; tt++) {
        // --- STS xh(tt) -> B (4x16B contiguous) ---
        {
            char* dst = bp + xc * 272 + kb * 2;
            uint4 v0 = { xh[0],  xh[1],  xh[2],  xh[3]  };
            uint4 v1 = { xh[4],  xh[5],  xh[6],  xh[7]  };
            uint4 v2 = { xh[8],  xh[9],  xh[10], xh[11] };
            uint4 v3 = { xh[12], xh[13], xh[14], xh[15] };
            *(uint4*)(dst)      = v0;
            *(uint4*)(dst + 16) = v1;
            *(uint4*)(dst + 32) = v2;
            *(uint4*)(dst + 48) = v3;
        }
        // --- coloff(tt+1) -> generation tt+1 ---
        if (tt + 1 < nt && tid < 64) {
            const int c  = (t0 + tt + 1) * 64 + tid;
            const int cc = c < ncols ? c : ncols - 1;
            const int b  = cc / span;
            coloff[(tt + 1) * 64 + tid] = b * XB_STRIDE + l * l + (cc - b * span);
        }
        __syncthreads();                          // sync1: B(tt)+coloff visible

        // --- LDG + convert X(tt+1) (lands during MMA below) ---
        if (tt + 1 < nt) {
            const float* xp = x + coloff[(tt + 1) * 64 + xc];
#pragma unroll
            for (int m = 0; m < 16; m++) {
                const __half h0 = __float2half_rn(xp[(kb + 2 * m) * P_TOT]);
                const __half h1 = __float2half_rn(xp[(kb + 2 * m + 1) * P_TOT]);
                xh[m] = ((unsigned)__half_as_ushort(h1) << 16) | __half_as_ushort(h0);
            }
        }

        // --- MMA: 8 k-steps, B-LDSM only, 8 independent acc chains ---
        float acc[8][4];
#pragma unroll
        for (int nq = 0; nq < 8; nq++)
#pragma unroll
            for (int j = 0; j < 4; j++) acc[nq][j] = 0.0f;

#pragma unroll
        for (int ks = 0; ks < 8; ks++) {
            const unsigned ko = (unsigned)ks * 32u;
            unsigned bf[4][4];
#pragma unroll
            for (int g = 0; g < 4; g++)
                LDSM4(bf[g], bB + (unsigned)g * (16u * 272u) + ko);
#pragma unroll
            for (int g = 0; g < 4; g++) {
                MMA16816(acc[2 * g],     aF[ks], bf[g][0], bf[g][1]);
                MMA16816(acc[2 * g + 1], aF[ks], bf[g][2], bf[g][3]);
            }
        }

        // --- STS acc -> EPI scratch (pitch 72, conflict-free STS.64) ---
        {
            const int r = m_base + (lane >> 2);
#pragma unroll
            for (int nq = 0; nq < 8; nq++) {
                const int cc = nq * 8 + (lane & 3) * 2;
                float2 lo = { acc[nq][0], acc[nq][1] };
                float2 hi = { acc[nq][2], acc[nq][3] };
                *(float2*)&ep[r * 72 + cc]       = lo;
                *(float2*)&ep[(r + 8) * 72 + cc] = hi;
            }
        }
        __syncthreads();                          // sync2: EPI complete

        // --- coalesced epilogue: lanes sweep consecutive c -> 128B lines ---
        if ((t0 + tt) * 64 + ec < ncols) {
            float* op = out + coloff[tt * 64 + ec] + ob * P_TOT;
            const float* rp = ep + ob * 72 + ec;
#pragma unroll
            for (int j = 0; j < 32; j++)
                op[j * 4 * P_TOT] = rp[j * 4 * 72];
        }
        // no third barrier: B rewritten only by same owner pattern after all
        // warps passed sync2; EPI rewritten only after next sync1; coloff
        // generation tt never rewritten within this CTA.
    }
}

extern "C" void kernel_launch(void* const* d_in, const int* in_sizes, int n_in,
                              void* d_out, int out_size)
{
    const float* x = (const float*)d_in[0];      // [16,128,6561]
    const float* w = (const float*)d_in[1];      // [128,128,17,1]
    float* out = (float*)d_out;                  // [16,128,6561]

    cudaFuncSetAttribute(shconv_mma,
                         cudaFuncAttributeMaxDynamicSharedMemorySize, DSMEM);

    shconv_interp_pack<<<512, 256>>>(w);

    dim3 grid(14, NDEG);                         // 3-tile chunks x degrees
    shconv_mma<<<grid, 256, DSMEM>>>(x, out);
}